// round 1
// baseline (speedup 1.0000x reference)
#include <cuda_runtime.h>

#define BDIM 2
#define LNUM 6
#define CDIM 128
#define NDIM 4096
#define NT 32                     // NDIM / 128
#define BL (BDIM*LNUM)
#define INV_SQRT (1.0f/64.0f)     // 1/sqrt(4096)

// ---------------- scratch (static device memory; allocation-free) ----------
__device__ float g_Q[(size_t)BL*NDIM*CDIM];            // [bl][n][c]
__device__ float g_K[(size_t)BL*NDIM*CDIM];            // [bl][m][c]
__device__ float g_G[(size_t)BL*NDIM*CDIM];            // [bl][m][c]
__device__ float g_S[(size_t)BL*NDIM*NDIM];            // [bl][m][n] raw scores (transposed vs ref)
__device__ float g_pmax[(size_t)BL*NDIM*NT];           // per (row, ntile) partial max
__device__ float g_psum[(size_t)BL*NDIM*NT];           // per (row, ntile) partial sum exp
__device__ float g_mu[(size_t)BL*NDIM];                // row max
__device__ float g_alpha[(size_t)BL*NDIM];             // 1/Z
__device__ float g_acc[(size_t)BL*CDIM*NDIM];          // [bl][c][n] per-layer partial out

// ---------------- kernel 1: projections Q/K/G = W @ x + b ------------------
// y[n][o] = sum_c W[o][c] * X[b][c][n] + bias[o]
__global__ void proj_kernel(const float* __restrict__ X,
                            const float* __restrict__ W1, const float* __restrict__ b1,
                            const float* __restrict__ W2, const float* __restrict__ b2,
                            const float* __restrict__ Wg, const float* __restrict__ bg)
{
    int bl = blockIdx.z;
    int b  = bl / LNUM;
    int l  = bl % LNUM;
    int p  = blockIdx.y;
    int n0 = blockIdx.x * 64;

    const float* W; const float* bias; float* dst;
    if (p == 0)      { W = W1; bias = b1; dst = g_Q; }
    else if (p == 1) { W = W2; bias = b2; dst = g_K; }
    else             { W = Wg; bias = bg; dst = g_G; }
    W    += (size_t)l * CDIM * CDIM;
    bias += l * CDIM;
    dst  += (size_t)bl * NDIM * CDIM;
    const float* Xb = X + (size_t)b * CDIM * NDIM;

    __shared__ float xs[32][64 + 1];     // [c][n]
    __shared__ float ws[32][CDIM + 4];   // [c][o]

    int tid = threadIdx.x;
    int tx = tid & 15;    // output-channel group (8 each)
    int ty = tid >> 4;    // token group (4 each)

    float acc[4][8];
    #pragma unroll
    for (int i = 0; i < 4; i++)
        #pragma unroll
        for (int j = 0; j < 8; j++) acc[i][j] = 0.f;

    for (int c0 = 0; c0 < CDIM; c0 += 32) {
        for (int i = tid; i < 32 * 64; i += 256) {
            int c = i >> 6, n = i & 63;
            xs[c][n] = Xb[(size_t)(c0 + c) * NDIM + n0 + n];
        }
        for (int i = tid; i < 32 * CDIM; i += 256) {
            int o = i >> 5, c = i & 31;
            ws[c][o] = W[o * CDIM + c0 + c];
        }
        __syncthreads();
        #pragma unroll
        for (int c = 0; c < 32; c++) {
            float a[4], bb[8];
            #pragma unroll
            for (int i = 0; i < 4; i++) a[i] = xs[c][ty * 4 + i];
            #pragma unroll
            for (int j = 0; j < 8; j++) bb[j] = ws[c][tx * 8 + j];
            #pragma unroll
            for (int i = 0; i < 4; i++)
                #pragma unroll
                for (int j = 0; j < 8; j++) acc[i][j] += a[i] * bb[j];
        }
        __syncthreads();
    }
    #pragma unroll
    for (int i = 0; i < 4; i++) {
        int n = n0 + ty * 4 + i;
        #pragma unroll
        for (int j = 0; j < 8; j++) {
            int o = tx * 8 + j;
            dst[(size_t)n * CDIM + o] = acc[i][j] + bias[o];
        }
    }
}

// ---------------- kernel 2: ST[m][n] = inv_sqrt * K[m]·Q[n], + tile stats ---
__global__ void score_kernel()
{
    int bl = blockIdx.z;
    int m0 = blockIdx.y * 128;
    int n0 = blockIdx.x * 128;
    const float* Kp = g_K + (size_t)bl * NDIM * CDIM;
    const float* Qp = g_Q + (size_t)bl * NDIM * CDIM;

    __shared__ float as[32][128 + 4];   // [c][m]
    __shared__ float bs[32][128 + 4];   // [c][n]

    int tid = threadIdx.x;
    int tx = tid & 15;    // n group
    int ty = tid >> 4;    // m group

    float acc[8][8];
    #pragma unroll
    for (int i = 0; i < 8; i++)
        #pragma unroll
        for (int j = 0; j < 8; j++) acc[i][j] = 0.f;

    for (int c0 = 0; c0 < CDIM; c0 += 32) {
        for (int i = tid; i < 128 * 32; i += 256) {
            int m = i >> 5, c = i & 31;
            as[c][m] = Kp[(size_t)(m0 + m) * CDIM + c0 + c];
        }
        for (int i = tid; i < 128 * 32; i += 256) {
            int n = i >> 5, c = i & 31;
            bs[c][n] = Qp[(size_t)(n0 + n) * CDIM + c0 + c];
        }
        __syncthreads();
        #pragma unroll
        for (int c = 0; c < 32; c++) {
            float a[8], bb[8];
            #pragma unroll
            for (int i = 0; i < 8; i++) a[i] = as[c][ty * 8 + i];
            #pragma unroll
            for (int j = 0; j < 8; j++) bb[j] = bs[c][tx * 8 + j];
            #pragma unroll
            for (int i = 0; i < 8; i++)
                #pragma unroll
                for (int j = 0; j < 8; j++) acc[i][j] += a[i] * bb[j];
        }
        __syncthreads();
    }

    #pragma unroll
    for (int i = 0; i < 8; i++)
        #pragma unroll
        for (int j = 0; j < 8; j++) acc[i][j] *= INV_SQRT;

    // write raw scores (vectorized)
    float* Sp = g_S + (size_t)bl * NDIM * NDIM;
    #pragma unroll
    for (int i = 0; i < 8; i++) {
        int m = m0 + ty * 8 + i;
        float4* dst = (float4*)&Sp[(size_t)m * NDIM + n0 + tx * 8];
        dst[0] = make_float4(acc[i][0], acc[i][1], acc[i][2], acc[i][3]);
        dst[1] = make_float4(acc[i][4], acc[i][5], acc[i][6], acc[i][7]);
    }

    // per-row partial stats within this 128-col tile.
    // lanes: tid = ty*16 + tx → within a warp, bits 0..3 = tx; xor-shuffle
    // over those bits reduces across the 16 columns groups of the same rows.
    #pragma unroll
    for (int i = 0; i < 8; i++) {
        float v = acc[i][0];
        #pragma unroll
        for (int j = 1; j < 8; j++) v = fmaxf(v, acc[i][j]);
        #pragma unroll
        for (int off = 1; off < 16; off <<= 1)
            v = fmaxf(v, __shfl_xor_sync(0xffffffffu, v, off));
        float s = 0.f;
        #pragma unroll
        for (int j = 0; j < 8; j++) s += __expf(acc[i][j] - v);
        #pragma unroll
        for (int off = 1; off < 16; off <<= 1)
            s += __shfl_xor_sync(0xffffffffu, s, off);
        if (tx == 0) {
            int m = m0 + ty * 8 + i;
            g_pmax[((size_t)bl * NDIM + m) * NT + blockIdx.x] = v;
            g_psum[((size_t)bl * NDIM + m) * NT + blockIdx.x] = s;
        }
    }
}

// ---------------- kernel 3: combine tile stats → mu, alpha per row ----------
__global__ void stats_kernel()
{
    int idx = blockIdx.x * blockDim.x + threadIdx.x;   // row over BL*NDIM
    if (idx >= BL * NDIM) return;
    const float* pm = &g_pmax[(size_t)idx * NT];
    const float* ps = &g_psum[(size_t)idx * NT];
    float mu = -1e30f;
    #pragma unroll
    for (int t = 0; t < NT; t++) mu = fmaxf(mu, pm[t]);
    float Z = 0.f;
    #pragma unroll
    for (int t = 0; t < NT; t++) Z += ps[t] * __expf(pm[t] - mu);
    g_mu[idx]    = mu;
    g_alpha[idx] = 1.f / Z;
}

// ---------------- kernel 4: acc[c][n] = sum_m (G[m][c]*alpha[m]) * exp(S[m][n]-mu[m])
__global__ void attnout_kernel()
{
    int bl = blockIdx.y;
    int n0 = blockIdx.x * 128;
    const float* Gp = g_G + (size_t)bl * NDIM * CDIM;
    const float* Sp = g_S + (size_t)bl * NDIM * NDIM;
    const float* mu = g_mu + (size_t)bl * NDIM;
    const float* al = g_alpha + (size_t)bl * NDIM;

    __shared__ float gs[32][CDIM + 4];   // [mi][c], alpha folded in
    __shared__ float ps[32][128 + 4];    // [mi][n], exp applied at load

    int tid = threadIdx.x;
    int tx = tid & 15;    // n group
    int ty = tid >> 4;    // c group

    float acc[8][8];
    #pragma unroll
    for (int i = 0; i < 8; i++)
        #pragma unroll
        for (int j = 0; j < 8; j++) acc[i][j] = 0.f;

    for (int mq = 0; mq < NDIM; mq += 32) {
        for (int i = tid; i < 32 * 128; i += 256) {
            int mi = i >> 7, c = i & 127;
            gs[mi][c] = Gp[(size_t)(mq + mi) * CDIM + c] * al[mq + mi];
        }
        for (int i = tid; i < 32 * 128; i += 256) {
            int mi = i >> 7, n = i & 127;
            ps[mi][n] = __expf(Sp[(size_t)(mq + mi) * NDIM + n0 + n] - mu[mq + mi]);
        }
        __syncthreads();
        #pragma unroll
        for (int mi = 0; mi < 32; mi++) {
            float a[8], bb[8];
            #pragma unroll
            for (int i = 0; i < 8; i++) a[i] = gs[mi][ty * 8 + i];
            #pragma unroll
            for (int j = 0; j < 8; j++) bb[j] = ps[mi][tx * 8 + j];
            #pragma unroll
            for (int i = 0; i < 8; i++)
                #pragma unroll
                for (int j = 0; j < 8; j++) acc[i][j] += a[i] * bb[j];
        }
        __syncthreads();
    }

    float* dst = g_acc + (size_t)bl * CDIM * NDIM;
    #pragma unroll
    for (int i = 0; i < 8; i++) {
        int c = ty * 8 + i;
        float4* d4 = (float4*)&dst[(size_t)c * NDIM + n0 + tx * 8];
        d4[0] = make_float4(acc[i][0], acc[i][1], acc[i][2], acc[i][3]);
        d4[1] = make_float4(acc[i][4], acc[i][5], acc[i][6], acc[i][7]);
    }
}

// ---------------- kernel 5: out = x + mean_l(acc) ---------------------------
__global__ void epilogue_kernel(const float* __restrict__ X, float* __restrict__ out)
{
    size_t idx = (size_t)blockIdx.x * blockDim.x + threadIdx.x;
    const size_t total = (size_t)BDIM * CDIM * NDIM;
    if (idx >= total) return;
    size_t b   = idx / ((size_t)CDIM * NDIM);
    size_t rem = idx % ((size_t)CDIM * NDIM);
    float s = 0.f;
    #pragma unroll
    for (int l = 0; l < LNUM; l++)
        s += g_acc[((size_t)(b * LNUM + l) * CDIM * NDIM) + rem];
    out[idx] = X[idx] + s * (1.0f / LNUM);
}

// ---------------- launch -----------------------------------------------------
extern "C" void kernel_launch(void* const* d_in, const int* in_sizes, int n_in,
                              void* d_out, int out_size)
{
    const float* x  = (const float*)d_in[0];
    const float* W1 = (const float*)d_in[1];
    const float* b1 = (const float*)d_in[2];
    const float* W2 = (const float*)d_in[3];
    const float* b2 = (const float*)d_in[4];
    const float* Wg = (const float*)d_in[5];
    const float* bg = (const float*)d_in[6];
    float* out = (float*)d_out;

    proj_kernel<<<dim3(NDIM / 64, 3, BL), 256>>>(x, W1, b1, W2, b2, Wg, bg);
    score_kernel<<<dim3(NT, NT, BL), 256>>>();
    stats_kernel<<<(BL * NDIM + 255) / 256, 256>>>();
    attnout_kernel<<<dim3(NT, BL), 256>>>();
    epilogue_kernel<<<(unsigned)(((size_t)BDIM * CDIM * NDIM + 255) / 256), 256>>>(x, out);
}

// round 4
// speedup vs baseline: 4.3783x; 4.3783x over previous
#include <cuda_runtime.h>
#include <cuda_bf16.h>
#include <cstdint>

#define BDIM 2
#define LNUM 6
#define CDIM 128
#define NDIM 4096
#define NT 32
#define BL (BDIM*LNUM)
#define INV_SQRT (1.0f/64.0f)

// ---------------- scratch (static device memory; allocation-free) ----------
__device__ __nv_bfloat16 g_Qb[(size_t)BL*NDIM*CDIM];   // [bl][n][c]
__device__ __nv_bfloat16 g_Kb[(size_t)BL*NDIM*CDIM];   // [bl][m][c]
__device__ __nv_bfloat16 g_Gt[(size_t)BL*CDIM*NDIM];   // [bl][c][m] (G transposed; alpha folded in later)
__device__ __nv_bfloat16 g_Sb[(size_t)BL*NDIM*NDIM];   // [bl][n][m] e = exp(s/64)
__device__ float g_psum[(size_t)BL*NDIM*NT];           // partial sum_n e per (m, ntile)
__device__ float g_alpha[(size_t)BL*NDIM];             // 1/Z per m
__device__ float g_acc[(size_t)BL*CDIM*NDIM];          // per-layer output [c][n]

// ---------------- helpers ----------------------------------------------------
__device__ __forceinline__ uint32_t smem_u32(const void* p) {
    uint32_t a;
    asm("{ .reg .u64 t; cvta.to.shared.u64 t, %1; cvt.u32.u64 %0, t; }" : "=r"(a) : "l"(p));
    return a;
}

// swizzled byte offset inside a [128 rows][256B] tile: chunk = 16B unit (0..15)
__device__ __forceinline__ uint32_t SWZ(int row, int chunk) {
    return (uint32_t)row * 256u + (uint32_t)((chunk ^ (row & 7)) << 4);
}

__device__ __forceinline__ void ldmx4(uint32_t* r, uint32_t addr) {
    asm volatile("ldmatrix.sync.aligned.m8n8.x4.shared.b16 {%0,%1,%2,%3}, [%4];"
        : "=r"(r[0]), "=r"(r[1]), "=r"(r[2]), "=r"(r[3]) : "r"(addr));
}

__device__ __forceinline__ void mma16816(float* d, const uint32_t* a, uint32_t b0, uint32_t b1) {
    asm volatile("mma.sync.aligned.m16n8k16.row.col.f32.bf16.bf16.f32 "
        "{%0,%1,%2,%3}, {%4,%5,%6,%7}, {%8,%9}, {%0,%1,%2,%3};"
        : "+f"(d[0]), "+f"(d[1]), "+f"(d[2]), "+f"(d[3])
        : "r"(a[0]), "r"(a[1]), "r"(a[2]), "r"(a[3]), "r"(b0), "r"(b1));
}

// ---------------- kernel 1: projections -> bf16 Q, K, Gt -------------------
__global__ void proj_kernel(const float* __restrict__ X,
                            const float* __restrict__ W1, const float* __restrict__ b1,
                            const float* __restrict__ W2, const float* __restrict__ b2,
                            const float* __restrict__ Wg, const float* __restrict__ bg)
{
    int bl = blockIdx.z;
    int b  = bl / LNUM;
    int l  = bl % LNUM;
    int p  = blockIdx.y;
    int n0 = blockIdx.x * 64;

    const float* W; const float* bias;
    if (p == 0)      { W = W1; bias = b1; }
    else if (p == 1) { W = W2; bias = b2; }
    else             { W = Wg; bias = bg; }
    W    += (size_t)l * CDIM * CDIM;
    bias += l * CDIM;
    const float* Xb = X + (size_t)b * CDIM * NDIM;

    __shared__ float xs[32][64 + 1];
    __shared__ float ws[32][CDIM + 4];

    int tid = threadIdx.x;
    int tx = tid & 15;
    int ty = tid >> 4;

    float acc[4][8];
    #pragma unroll
    for (int i = 0; i < 4; i++)
        #pragma unroll
        for (int j = 0; j < 8; j++) acc[i][j] = 0.f;

    for (int c0 = 0; c0 < CDIM; c0 += 32) {
        for (int i = tid; i < 32 * 64; i += 256) {
            int c = i >> 6, n = i & 63;
            xs[c][n] = Xb[(size_t)(c0 + c) * NDIM + n0 + n];
        }
        for (int i = tid; i < 32 * CDIM; i += 256) {
            int o = i >> 5, c = i & 31;
            ws[c][o] = W[o * CDIM + c0 + c];
        }
        __syncthreads();
        #pragma unroll
        for (int c = 0; c < 32; c++) {
            float a[4], bb[8];
            #pragma unroll
            for (int i = 0; i < 4; i++) a[i] = xs[c][ty * 4 + i];
            #pragma unroll
            for (int j = 0; j < 8; j++) bb[j] = ws[c][tx * 8 + j];
            #pragma unroll
            for (int i = 0; i < 4; i++)
                #pragma unroll
                for (int j = 0; j < 8; j++) acc[i][j] += a[i] * bb[j];
        }
        __syncthreads();
    }

    if (p < 2) {
        __nv_bfloat16* dst = (p == 0 ? g_Qb : g_Kb) + (size_t)bl * NDIM * CDIM;
        #pragma unroll
        for (int i = 0; i < 4; i++) {
            int n = n0 + ty * 4 + i;
            #pragma unroll
            for (int j = 0; j < 8; j++) {
                int o = tx * 8 + j;
                dst[(size_t)n * CDIM + o] = __float2bfloat16(acc[i][j] + bias[o]);
            }
        }
    } else {
        __nv_bfloat16* dst = g_Gt + (size_t)bl * CDIM * NDIM;   // [c][n]
        #pragma unroll
        for (int i = 0; i < 4; i++) {
            int n = n0 + ty * 4 + i;
            #pragma unroll
            for (int j = 0; j < 8; j++) {
                int o = tx * 8 + j;
                dst[(size_t)o * NDIM + n] = __float2bfloat16(acc[i][j] + bias[o]);
            }
        }
    }
}

// ---------------- kernel 2: scores via mma.sync ------------------------------
// C[n][m] = q_n . k_m ; e = exp(C/64) -> Sb[n][m] bf16; psum[m][ntile] = sum_n e
#define SMEM_SCORE (65536 + 1024)
__global__ __launch_bounds__(256) void score_kernel()
{
    extern __shared__ char sm[];
    uint32_t sbA = smem_u32(sm);
    uint32_t sbB = sbA + 32768;
    float* red = (float*)(sm + 65536);

    int tid = threadIdx.x, lane = tid & 31, w = tid >> 5;
    int wn = w >> 2, wm = w & 3;                 // 2 x 4 warp grid
    int bl = blockIdx.z, m0 = blockIdx.y * 128, n0 = blockIdx.x * 128;

    const __nv_bfloat16* Qp = g_Qb + (size_t)bl * NDIM * CDIM;
    const __nv_bfloat16* Kp = g_Kb + (size_t)bl * NDIM * CDIM;

    #pragma unroll
    for (int it = 0; it < 8; it++) {
        int s = tid + it * 256;
        int row = s >> 4, ch = s & 15;
        *(uint4*)(sm + SWZ(row, ch))         = *(const uint4*)(Qp + (size_t)(n0 + row) * CDIM + ch * 8);
        *(uint4*)(sm + 32768 + SWZ(row, ch)) = *(const uint4*)(Kp + (size_t)(m0 + row) * CDIM + ch * 8);
    }
    __syncthreads();

    float acc[4][4][4];
    #pragma unroll
    for (int i = 0; i < 4; i++)
        #pragma unroll
        for (int j = 0; j < 4; j++)
            #pragma unroll
            for (int q = 0; q < 4; q++) acc[i][j][q] = 0.f;

    #pragma unroll
    for (int ks = 0; ks < 8; ks++) {
        uint32_t a[4][4], b[2][4];
        #pragma unroll
        for (int mi = 0; mi < 4; mi++)
            ldmx4(a[mi], sbA + SWZ(wn * 64 + mi * 16 + (lane & 15), 2 * ks + (lane >> 4)));
        #pragma unroll
        for (int q = 0; q < 2; q++)
            ldmx4(b[q], sbB + SWZ(wm * 32 + q * 16 + (lane & 7) + ((lane >> 4) << 3),
                                  2 * ks + ((lane >> 3) & 1)));
        #pragma unroll
        for (int mi = 0; mi < 4; mi++)
            #pragma unroll
            for (int q = 0; q < 2; q++) {
                mma16816(acc[mi][2 * q],     a[mi], b[q][0], b[q][1]);
                mma16816(acc[mi][2 * q + 1], a[mi], b[q][2], b[q][3]);
            }
    }

    int gid = lane >> 2, tig = lane & 3;
    float ss[4][2];
    #pragma unroll
    for (int nj = 0; nj < 4; nj++) { ss[nj][0] = 0.f; ss[nj][1] = 0.f; }

    __nv_bfloat16* Sp = g_Sb + (size_t)bl * NDIM * NDIM;
    #pragma unroll
    for (int mi = 0; mi < 4; mi++) {
        int nr0 = n0 + wn * 64 + mi * 16 + gid;
        #pragma unroll
        for (int nj = 0; nj < 4; nj++) {
            int mc = m0 + wm * 32 + nj * 8 + 2 * tig;
            float e0 = __expf(acc[mi][nj][0] * INV_SQRT);
            float e1 = __expf(acc[mi][nj][1] * INV_SQRT);
            float e2 = __expf(acc[mi][nj][2] * INV_SQRT);
            float e3 = __expf(acc[mi][nj][3] * INV_SQRT);
            __nv_bfloat162 h01, h23;
            h01.x = __float2bfloat16(e0); h01.y = __float2bfloat16(e1);
            h23.x = __float2bfloat16(e2); h23.y = __float2bfloat16(e3);
            *(__nv_bfloat162*)(Sp + (size_t)nr0 * NDIM + mc)       = h01;
            *(__nv_bfloat162*)(Sp + (size_t)(nr0 + 8) * NDIM + mc) = h23;
            // psum from ROUNDED values for exact softmax consistency
            ss[nj][0] += __bfloat162float(h01.x) + __bfloat162float(h23.x);
            ss[nj][1] += __bfloat162float(h01.y) + __bfloat162float(h23.y);
        }
    }

    // reduce over gid (lanes sharing tig)
    #pragma unroll
    for (int nj = 0; nj < 4; nj++) {
        #pragma unroll
        for (int off = 4; off < 32; off <<= 1) {
            ss[nj][0] += __shfl_xor_sync(0xffffffffu, ss[nj][0], off);
            ss[nj][1] += __shfl_xor_sync(0xffffffffu, ss[nj][1], off);
        }
    }
    if (lane < 4) {
        #pragma unroll
        for (int nj = 0; nj < 4; nj++) {
            red[wn * 128 + wm * 32 + nj * 8 + 2 * tig]     = ss[nj][0];
            red[wn * 128 + wm * 32 + nj * 8 + 2 * tig + 1] = ss[nj][1];
        }
    }
    __syncthreads();
    if (tid < 128)
        g_psum[((size_t)bl * NDIM + m0 + tid) * NT + blockIdx.x] = red[tid] + red[128 + tid];
}

// ---------------- kernel 3: alpha = 1/Z -------------------------------------
__global__ void stats_kernel()
{
    int idx = blockIdx.x * blockDim.x + threadIdx.x;
    if (idx >= BL * NDIM) return;
    const float* ps = g_psum + (size_t)idx * NT;
    float Z = 0.f;
    #pragma unroll
    for (int t = 0; t < NT; t++) Z += ps[t];
    g_alpha[idx] = 1.f / Z;
}

// ---------------- kernel 3b: fold alpha into Gt (in place) ------------------
__global__ void scale_kernel()
{
    size_t v = (size_t)blockIdx.x * blockDim.x + threadIdx.x;     // uint4 index
    const size_t nvec = (size_t)BL * CDIM * NDIM / 8;
    if (v >= nvec) return;
    size_t e0 = v * 8;
    size_t bl = e0 / ((size_t)CDIM * NDIM);
    size_t m  = e0 % NDIM;
    const float* al = g_alpha + bl * NDIM + m;
    uint4 u = *(uint4*)(g_Gt + e0);
    __nv_bfloat162* h = (__nv_bfloat162*)&u;
    #pragma unroll
    for (int j = 0; j < 4; j++) {
        float2 f = __bfloat1622float2(h[j]);
        h[j].x = __float2bfloat16(f.x * al[2 * j]);
        h[j].y = __float2bfloat16(f.y * al[2 * j + 1]);
    }
    *(uint4*)(g_Gt + e0) = u;
}

// ---------------- kernel 4: acc[c][n] = sum_m Gta[c][m] * e[n][m] ------------
__global__ __launch_bounds__(256) void attnout_kernel()
{
    extern __shared__ char sm[];
    uint32_t sbA = smem_u32(sm);
    uint32_t sbB = sbA + 32768;

    int tid = threadIdx.x, lane = tid & 31, w = tid >> 5;
    int wc = w >> 2, wn = w & 3;                 // 2(c) x 4(n) warp grid
    int bl = blockIdx.y, n0 = blockIdx.x * 128;

    const __nv_bfloat16* Gp = g_Gt + (size_t)bl * CDIM * NDIM;
    const __nv_bfloat16* Sp = g_Sb + (size_t)bl * NDIM * NDIM;

    float acc[4][4][4];
    #pragma unroll
    for (int i = 0; i < 4; i++)
        #pragma unroll
        for (int j = 0; j < 4; j++)
            #pragma unroll
            for (int q = 0; q < 4; q++) acc[i][j][q] = 0.f;

    for (int chk = 0; chk < 32; chk++) {
        int mq = chk * 128;
        if (chk) __syncthreads();
        #pragma unroll
        for (int it = 0; it < 8; it++) {
            int s = tid + it * 256;
            int row = s >> 4, ch = s & 15;
            *(uint4*)(sm + SWZ(row, ch))         = *(const uint4*)(Gp + (size_t)row * NDIM + mq + ch * 8);
            *(uint4*)(sm + 32768 + SWZ(row, ch)) = *(const uint4*)(Sp + (size_t)(n0 + row) * NDIM + mq + ch * 8);
        }
        __syncthreads();

        #pragma unroll
        for (int ks = 0; ks < 8; ks++) {
            uint32_t a[4][4], b[2][4];
            #pragma unroll
            for (int mi = 0; mi < 4; mi++)
                ldmx4(a[mi], sbA + SWZ(wc * 64 + mi * 16 + (lane & 15), 2 * ks + (lane >> 4)));
            #pragma unroll
            for (int q = 0; q < 2; q++)
                ldmx4(b[q], sbB + SWZ(wn * 32 + q * 16 + (lane & 7) + ((lane >> 4) << 3),
                                      2 * ks + ((lane >> 3) & 1)));
            #pragma unroll
            for (int mi = 0; mi < 4; mi++)
                #pragma unroll
                for (int q = 0; q < 2; q++) {
                    mma16816(acc[mi][2 * q],     a[mi], b[q][0], b[q][1]);
                    mma16816(acc[mi][2 * q + 1], a[mi], b[q][2], b[q][3]);
                }
        }
    }

    int gid = lane >> 2, tig = lane & 3;
    float* dstb = g_acc + (size_t)bl * CDIM * NDIM;
    #pragma unroll
    for (int mi = 0; mi < 4; mi++) {
        int c0 = wc * 64 + mi * 16 + gid;
        #pragma unroll
        for (int nj = 0; nj < 4; nj++) {
            int n = n0 + wn * 32 + nj * 8 + 2 * tig;
            *(float2*)(dstb + (size_t)c0 * NDIM + n)       = make_float2(acc[mi][nj][0], acc[mi][nj][1]);
            *(float2*)(dstb + (size_t)(c0 + 8) * NDIM + n) = make_float2(acc[mi][nj][2], acc[mi][nj][3]);
        }
    }
}

// ---------------- kernel 5: out = x + mean_l(acc) ---------------------------
__global__ void epilogue_kernel(const float* __restrict__ X, float* __restrict__ out)
{
    size_t idx = (size_t)blockIdx.x * blockDim.x + threadIdx.x;
    const size_t total = (size_t)BDIM * CDIM * NDIM;
    if (idx >= total) return;
    size_t b   = idx / ((size_t)CDIM * NDIM);
    size_t rem = idx % ((size_t)CDIM * NDIM);
    float s = 0.f;
    #pragma unroll
    for (int l = 0; l < LNUM; l++)
        s += g_acc[((size_t)(b * LNUM + l) * CDIM * NDIM) + rem];
    out[idx] = X[idx] + s * (1.0f / LNUM);
}

// ---------------- launch -----------------------------------------------------
extern "C" void kernel_launch(void* const* d_in, const int* in_sizes, int n_in,
                              void* d_out, int out_size)
{
    const float* x  = (const float*)d_in[0];
    const float* W1 = (const float*)d_in[1];
    const float* b1 = (const float*)d_in[2];
    const float* W2 = (const float*)d_in[3];
    const float* b2 = (const float*)d_in[4];
    const float* Wg = (const float*)d_in[5];
    const float* bg = (const float*)d_in[6];
    float* out = (float*)d_out;

    cudaFuncSetAttribute(score_kernel,   cudaFuncAttributeMaxDynamicSharedMemorySize, SMEM_SCORE);
    cudaFuncSetAttribute(attnout_kernel, cudaFuncAttributeMaxDynamicSharedMemorySize, 65536);

    proj_kernel<<<dim3(NDIM / 64, 3, BL), 256>>>(x, W1, b1, W2, b2, Wg, bg);
    score_kernel<<<dim3(NT, NT, BL), 256, SMEM_SCORE>>>();
    stats_kernel<<<(BL * NDIM + 255) / 256, 256>>>();
    scale_kernel<<<(unsigned)(((size_t)BL * CDIM * NDIM / 8 + 255) / 256), 256>>>();
    attnout_kernel<<<dim3(NT, BL), 256, 65536>>>();
    epilogue_kernel<<<(unsigned)(((size_t)BDIM * CDIM * NDIM + 255) / 256), 256>>>(x, out);
}

// round 5
// speedup vs baseline: 6.5538x; 1.4969x over previous
#include <cuda_runtime.h>
#include <cuda_bf16.h>
#include <cstdint>

#define BDIM 2
#define LNUM 6
#define CDIM 128
#define NDIM 4096
#define NT 32
#define BL (BDIM*LNUM)
#define INV_SQRT (1.0f/64.0f)

// ---------------- scratch (static device memory; allocation-free) ----------
__device__ __nv_bfloat16 g_Qb[(size_t)BL*NDIM*CDIM];   // [bl][n][c]
__device__ __nv_bfloat16 g_Kb[(size_t)BL*NDIM*CDIM];   // [bl][m][c]
__device__ __nv_bfloat16 g_Gt[(size_t)BL*CDIM*NDIM];   // [bl][c][m] (alpha folded in by scale_kernel)
__device__ __nv_bfloat16 g_Sb[(size_t)BL*NDIM*NDIM];   // [bl][n][m] e = exp(s/64)
__device__ float g_psum[(size_t)BL*NDIM*NT];           // partial sum_n e per (m, ntile)
__device__ float g_alpha[(size_t)BL*NDIM];             // 1/Z per m
__device__ float g_acc[(size_t)BL*2*CDIM*NDIM];        // per-(layer,split) output [c][n]

// ---------------- helpers ----------------------------------------------------
__device__ __forceinline__ uint32_t smem_u32(const void* p) {
    uint32_t a;
    asm("{ .reg .u64 t; cvta.to.shared.u64 t, %1; cvt.u32.u64 %0, t; }" : "=r"(a) : "l"(p));
    return a;
}

// swizzled byte offset inside [128 rows][256B] tile: chunk = 16B unit (0..15)
__device__ __forceinline__ uint32_t SWZ(int row, int chunk) {
    return (uint32_t)row * 256u + (uint32_t)((chunk ^ (row & 7)) << 4);
}
// swizzled byte offset inside [128 rows][128B] tile: chunk = 16B unit (0..7)
__device__ __forceinline__ uint32_t SWZ8(int row, int chunk) {
    return (uint32_t)row * 128u + (uint32_t)((chunk ^ (row & 7)) << 4);
}

__device__ __forceinline__ void ldmx4(uint32_t* r, uint32_t addr) {
    asm volatile("ldmatrix.sync.aligned.m8n8.x4.shared.b16 {%0,%1,%2,%3}, [%4];"
        : "=r"(r[0]), "=r"(r[1]), "=r"(r[2]), "=r"(r[3]) : "r"(addr));
}

__device__ __forceinline__ void mma16816(float* d, const uint32_t* a, uint32_t b0, uint32_t b1) {
    asm volatile("mma.sync.aligned.m16n8k16.row.col.f32.bf16.bf16.f32 "
        "{%0,%1,%2,%3}, {%4,%5,%6,%7}, {%8,%9}, {%0,%1,%2,%3};"
        : "+f"(d[0]), "+f"(d[1]), "+f"(d[2]), "+f"(d[3])
        : "r"(a[0]), "r"(a[1]), "r"(a[2]), "r"(a[3]), "r"(b0), "r"(b1));
}

#define CP_ASYNC16(dst, src) \
    asm volatile("cp.async.cg.shared.global [%0], [%1], 16;" :: "r"(dst), "l"(src))
#define CP_COMMIT() asm volatile("cp.async.commit_group;" ::: "memory")
#define CP_WAIT(n)  asm volatile("cp.async.wait_group %0;" :: "n"(n) : "memory")

// ---------------- kernel 1: projections -> bf16 Q, K, Gt -------------------
__global__ void proj_kernel(const float* __restrict__ X,
                            const float* __restrict__ W1, const float* __restrict__ b1,
                            const float* __restrict__ W2, const float* __restrict__ b2,
                            const float* __restrict__ Wg, const float* __restrict__ bg)
{
    int bl = blockIdx.z;
    int b  = bl / LNUM;
    int l  = bl % LNUM;
    int p  = blockIdx.y;
    int n0 = blockIdx.x * 64;

    const float* W; const float* bias;
    if (p == 0)      { W = W1; bias = b1; }
    else if (p == 1) { W = W2; bias = b2; }
    else             { W = Wg; bias = bg; }
    W    += (size_t)l * CDIM * CDIM;
    bias += l * CDIM;
    const float* Xb = X + (size_t)b * CDIM * NDIM;

    __shared__ float xs[32][64 + 1];
    __shared__ float ws[32][CDIM + 4];

    int tid = threadIdx.x;
    int tx = tid & 15;
    int ty = tid >> 4;

    float acc[4][8];
    #pragma unroll
    for (int i = 0; i < 4; i++)
        #pragma unroll
        for (int j = 0; j < 8; j++) acc[i][j] = 0.f;

    for (int c0 = 0; c0 < CDIM; c0 += 32) {
        for (int i = tid; i < 32 * 64; i += 256) {
            int c = i >> 6, n = i & 63;
            xs[c][n] = Xb[(size_t)(c0 + c) * NDIM + n0 + n];
        }
        for (int i = tid; i < 32 * CDIM; i += 256) {
            int o = i >> 5, c = i & 31;
            ws[c][o] = W[o * CDIM + c0 + c];
        }
        __syncthreads();
        #pragma unroll
        for (int c = 0; c < 32; c++) {
            float a[4], bb[8];
            #pragma unroll
            for (int i = 0; i < 4; i++) a[i] = xs[c][ty * 4 + i];
            #pragma unroll
            for (int j = 0; j < 8; j++) bb[j] = ws[c][tx * 8 + j];
            #pragma unroll
            for (int i = 0; i < 4; i++)
                #pragma unroll
                for (int j = 0; j < 8; j++) acc[i][j] += a[i] * bb[j];
        }
        __syncthreads();
    }

    if (p < 2) {
        __nv_bfloat16* dst = (p == 0 ? g_Qb : g_Kb) + (size_t)bl * NDIM * CDIM;
        #pragma unroll
        for (int i = 0; i < 4; i++) {
            int n = n0 + ty * 4 + i;
            #pragma unroll
            for (int j = 0; j < 8; j++) {
                int o = tx * 8 + j;
                dst[(size_t)n * CDIM + o] = __float2bfloat16(acc[i][j] + bias[o]);
            }
        }
    } else {
        __nv_bfloat16* dst = g_Gt + (size_t)bl * CDIM * NDIM;   // [c][n]
        #pragma unroll
        for (int i = 0; i < 4; i++) {
            int n = n0 + ty * 4 + i;
            #pragma unroll
            for (int j = 0; j < 8; j++) {
                int o = tx * 8 + j;
                dst[(size_t)o * NDIM + n] = __float2bfloat16(acc[i][j] + bias[o]);
            }
        }
    }
}

// ---------------- kernel 2: scores via mma.sync ------------------------------
// C[n][m] = q_n . k_m ; e = exp(C/64) -> Sb[n][m] bf16 (smem-staged coalesced
// stores); psum[m][ntile] = sum_n e
#define SMEM_SCORE (65536 + 1024)
__global__ __launch_bounds__(256) void score_kernel()
{
    extern __shared__ char sm[];
    uint32_t sbA = smem_u32(sm);
    uint32_t sbB = sbA + 32768;
    float* red = (float*)(sm + 65536);

    int tid = threadIdx.x, lane = tid & 31, w = tid >> 5;
    int wn = w >> 2, wm = w & 3;                 // 2 x 4 warp grid
    int bl = blockIdx.z, m0 = blockIdx.y * 128, n0 = blockIdx.x * 128;

    const __nv_bfloat16* Qp = g_Qb + (size_t)bl * NDIM * CDIM;
    const __nv_bfloat16* Kp = g_Kb + (size_t)bl * NDIM * CDIM;

    #pragma unroll
    for (int it = 0; it < 8; it++) {
        int s = tid + it * 256;
        int row = s >> 4, ch = s & 15;
        CP_ASYNC16(sbA + SWZ(row, ch), Qp + (size_t)(n0 + row) * CDIM + ch * 8);
        CP_ASYNC16(sbB + SWZ(row, ch), Kp + (size_t)(m0 + row) * CDIM + ch * 8);
    }
    CP_COMMIT();
    CP_WAIT(0);
    __syncthreads();

    float acc[4][4][4];
    #pragma unroll
    for (int i = 0; i < 4; i++)
        #pragma unroll
        for (int j = 0; j < 4; j++)
            #pragma unroll
            for (int q = 0; q < 4; q++) acc[i][j][q] = 0.f;

    #pragma unroll
    for (int ks = 0; ks < 8; ks++) {
        uint32_t a[4][4], b[2][4];
        #pragma unroll
        for (int mi = 0; mi < 4; mi++)
            ldmx4(a[mi], sbA + SWZ(wn * 64 + mi * 16 + (lane & 15), 2 * ks + (lane >> 4)));
        #pragma unroll
        for (int q = 0; q < 2; q++)
            ldmx4(b[q], sbB + SWZ(wm * 32 + q * 16 + (lane & 7) + ((lane >> 4) << 3),
                                  2 * ks + ((lane >> 3) & 1)));
        #pragma unroll
        for (int mi = 0; mi < 4; mi++)
            #pragma unroll
            for (int q = 0; q < 2; q++) {
                mma16816(acc[mi][2 * q],     a[mi], b[q][0], b[q][1]);
                mma16816(acc[mi][2 * q + 1], a[mi], b[q][2], b[q][3]);
            }
    }

    int gid = lane >> 2, tig = lane & 3;
    float ss[4][2];
    #pragma unroll
    for (int nj = 0; nj < 4; nj++) { ss[nj][0] = 0.f; ss[nj][1] = 0.f; }

    __syncthreads();   // all warps done reading operand smem; reuse sbA as e-tile

    // e-tile staging in smem: [128 n-rows][128 m cols * 2B = 256B], SWZ layout
    #pragma unroll
    for (int mi = 0; mi < 4; mi++) {
        int r0 = wn * 64 + mi * 16 + gid;
        #pragma unroll
        for (int nj = 0; nj < 4; nj++) {
            float e0 = __expf(acc[mi][nj][0] * INV_SQRT);
            float e1 = __expf(acc[mi][nj][1] * INV_SQRT);
            float e2 = __expf(acc[mi][nj][2] * INV_SQRT);
            float e3 = __expf(acc[mi][nj][3] * INV_SQRT);
            __nv_bfloat162 h01, h23;
            h01.x = __float2bfloat16(e0); h01.y = __float2bfloat16(e1);
            h23.x = __float2bfloat16(e2); h23.y = __float2bfloat16(e3);
            int chn = wm * 4 + nj;
            *(__nv_bfloat162*)(sm + SWZ(r0, chn) + tig * 4)     = h01;
            *(__nv_bfloat162*)(sm + SWZ(r0 + 8, chn) + tig * 4) = h23;
            // psum from ROUNDED values for exact softmax consistency
            ss[nj][0] += __bfloat162float(h01.x) + __bfloat162float(h23.x);
            ss[nj][1] += __bfloat162float(h01.y) + __bfloat162float(h23.y);
        }
    }

    // reduce over gid (lanes sharing tig)
    #pragma unroll
    for (int nj = 0; nj < 4; nj++) {
        #pragma unroll
        for (int off = 4; off < 32; off <<= 1) {
            ss[nj][0] += __shfl_xor_sync(0xffffffffu, ss[nj][0], off);
            ss[nj][1] += __shfl_xor_sync(0xffffffffu, ss[nj][1], off);
        }
    }
    if (lane < 4) {
        #pragma unroll
        for (int nj = 0; nj < 4; nj++) {
            red[wn * 128 + wm * 32 + nj * 8 + 2 * tig]     = ss[nj][0];
            red[wn * 128 + wm * 32 + nj * 8 + 2 * tig + 1] = ss[nj][1];
        }
    }
    __syncthreads();

    // coalesced Sb store (128B per 16 lanes)
    __nv_bfloat16* Sp = g_Sb + (size_t)bl * NDIM * NDIM;
    #pragma unroll
    for (int it = 0; it < 8; it++) {
        int s = tid + it * 256;
        int row = s >> 4, ch = s & 15;
        *(uint4*)(Sp + (size_t)(n0 + row) * NDIM + m0 + ch * 8) = *(uint4*)(sm + SWZ(row, ch));
    }
    if (tid < 128)
        g_psum[((size_t)bl * NDIM + m0 + tid) * NT + blockIdx.x] = red[tid] + red[128 + tid];
}

// ---------------- kernel 3: alpha = 1/Z -------------------------------------
__global__ void stats_kernel()
{
    int idx = blockIdx.x * blockDim.x + threadIdx.x;
    if (idx >= BL * NDIM) return;
    const float* ps = g_psum + (size_t)idx * NT;
    float Z = 0.f;
    #pragma unroll
    for (int t = 0; t < NT; t++) Z += ps[t];
    g_alpha[idx] = 1.f / Z;
}

// ---------------- kernel 3b: fold alpha into Gt (in place) ------------------
__global__ void scale_kernel()
{
    size_t v = (size_t)blockIdx.x * blockDim.x + threadIdx.x;     // uint4 index
    const size_t nvec = (size_t)BL * CDIM * NDIM / 8;
    if (v >= nvec) return;
    size_t e0 = v * 8;
    size_t bl = e0 / ((size_t)CDIM * NDIM);
    size_t m  = e0 % NDIM;
    const float* al = g_alpha + bl * NDIM + m;
    uint4 u = *(uint4*)(g_Gt + e0);
    __nv_bfloat162* h = (__nv_bfloat162*)&u;
    #pragma unroll
    for (int j = 0; j < 4; j++) {
        float2 f = __bfloat1622float2(h[j]);
        h[j].x = __float2bfloat16(f.x * al[2 * j]);
        h[j].y = __float2bfloat16(f.y * al[2 * j + 1]);
    }
    *(uint4*)(g_Gt + e0) = u;
}

// ---------------- kernel 4: acc[c][n] = sum_m Gta[c][m] * e[n][m] ------------
// 3-stage cp.async pipeline over KC=64 m-chunks; split-k = 2 over blockIdx.z
#define KC 64
#define NC 32                          // 2048 / KC chunks per CTA
#define STG_BYTES 32768                // 16KB A + 16KB B
#define SMEM_ATT (3 * STG_BYTES)
__global__ __launch_bounds__(256, 2) void attnout_kernel()
{
    extern __shared__ char sm[];
    uint32_t sb = smem_u32(sm);

    int tid = threadIdx.x, lane = tid & 31, w = tid >> 5;
    int wc = w >> 2, wn = w & 3;                 // 2(c) x 4(n) warp grid
    int bl = blockIdx.y, n0 = blockIdx.x * 128;
    int mbase = blockIdx.z * 2048;

    const __nv_bfloat16* Gp = g_Gt + (size_t)bl * CDIM * NDIM;
    const __nv_bfloat16* Sp = g_Sb + (size_t)bl * NDIM * NDIM;

    int lrow = tid >> 3, lch = tid & 7;          // loader: 32 rows per iter x 8 chunks

    // prologue: fill 3 stages
    #pragma unroll
    for (int p = 0; p < 3; p++) {
        int mq = mbase + p * KC;
        uint32_t sA = sb + p * STG_BYTES, sB = sA + 16384;
        #pragma unroll
        for (int it = 0; it < 4; it++) {
            int row = lrow + it * 32;
            CP_ASYNC16(sA + SWZ8(row, lch), Gp + (size_t)row * NDIM + mq + lch * 8);
            CP_ASYNC16(sB + SWZ8(row, lch), Sp + (size_t)(n0 + row) * NDIM + mq + lch * 8);
        }
        CP_COMMIT();
    }

    float acc[4][4][4];
    #pragma unroll
    for (int i = 0; i < 4; i++)
        #pragma unroll
        for (int j = 0; j < 4; j++)
            #pragma unroll
            for (int q = 0; q < 4; q++) acc[i][j][q] = 0.f;

    int st = 0;
    for (int chk = 0; chk < NC; chk++) {
        CP_WAIT(2);                // oldest group (this chunk) complete
        __syncthreads();

        uint32_t sA = sb + st * STG_BYTES, sB = sA + 16384;
        #pragma unroll
        for (int ks = 0; ks < 4; ks++) {
            uint32_t a[4][4], b[2][4];
            #pragma unroll
            for (int mi = 0; mi < 4; mi++)
                ldmx4(a[mi], sA + SWZ8(wc * 64 + mi * 16 + (lane & 15), 2 * ks + (lane >> 4)));
            #pragma unroll
            for (int q = 0; q < 2; q++)
                ldmx4(b[q], sB + SWZ8(wn * 32 + q * 16 + (lane & 7) + ((lane >> 4) << 3),
                                      2 * ks + ((lane >> 3) & 1)));
            #pragma unroll
            for (int mi = 0; mi < 4; mi++)
                #pragma unroll
                for (int q = 0; q < 2; q++) {
                    mma16816(acc[mi][2 * q],     a[mi], b[q][0], b[q][1]);
                    mma16816(acc[mi][2 * q + 1], a[mi], b[q][2], b[q][3]);
                }
        }
        __syncthreads();           // all warps done with stage st before refill

        if (chk + 3 < NC) {
            int mq = mbase + (chk + 3) * KC;
            #pragma unroll
            for (int it = 0; it < 4; it++) {
                int row = lrow + it * 32;
                CP_ASYNC16(sA + SWZ8(row, lch), Gp + (size_t)row * NDIM + mq + lch * 8);
                CP_ASYNC16(sB + SWZ8(row, lch), Sp + (size_t)(n0 + row) * NDIM + mq + lch * 8);
            }
        }
        CP_COMMIT();               // commit every iter (possibly empty) to keep counts aligned
        st = (st + 1 == 3) ? 0 : st + 1;
    }

    int gid = lane >> 2, tig = lane & 3;
    float* dstb = g_acc + ((size_t)(bl * 2 + blockIdx.z)) * CDIM * NDIM;
    #pragma unroll
    for (int mi = 0; mi < 4; mi++) {
        int c0 = wc * 64 + mi * 16 + gid;
        #pragma unroll
        for (int nj = 0; nj < 4; nj++) {
            int n = n0 + wn * 32 + nj * 8 + 2 * tig;
            *(float2*)(dstb + (size_t)c0 * NDIM + n)       = make_float2(acc[mi][nj][0], acc[mi][nj][1]);
            *(float2*)(dstb + (size_t)(c0 + 8) * NDIM + n) = make_float2(acc[mi][nj][2], acc[mi][nj][3]);
        }
    }
}

// ---------------- kernel 5: out = x + mean_l(acc) ---------------------------
__global__ void epilogue_kernel(const float* __restrict__ X, float* __restrict__ out)
{
    size_t idx = (size_t)blockIdx.x * blockDim.x + threadIdx.x;
    const size_t total = (size_t)BDIM * CDIM * NDIM;
    if (idx >= total) return;
    size_t b   = idx / ((size_t)CDIM * NDIM);
    size_t rem = idx % ((size_t)CDIM * NDIM);
    float s = 0.f;
    #pragma unroll
    for (int l = 0; l < LNUM; l++) {
        size_t base = ((size_t)(b * LNUM + l) * 2) * CDIM * NDIM;
        s += g_acc[base + rem] + g_acc[base + (size_t)CDIM * NDIM + rem];
    }
    out[idx] = X[idx] + s * (1.0f / LNUM);
}

// ---------------- launch -----------------------------------------------------
extern "C" void kernel_launch(void* const* d_in, const int* in_sizes, int n_in,
                              void* d_out, int out_size)
{
    const float* x  = (const float*)d_in[0];
    const float* W1 = (const float*)d_in[1];
    const float* b1 = (const float*)d_in[2];
    const float* W2 = (const float*)d_in[3];
    const float* b2 = (const float*)d_in[4];
    const float* Wg = (const float*)d_in[5];
    const float* bg = (const float*)d_in[6];
    float* out = (float*)d_out;

    cudaFuncSetAttribute(score_kernel,   cudaFuncAttributeMaxDynamicSharedMemorySize, SMEM_SCORE);
    cudaFuncSetAttribute(attnout_kernel, cudaFuncAttributeMaxDynamicSharedMemorySize, SMEM_ATT);

    proj_kernel<<<dim3(NDIM / 64, 3, BL), 256>>>(x, W1, b1, W2, b2, Wg, bg);
    score_kernel<<<dim3(NT, NT, BL), 256, SMEM_SCORE>>>();
    stats_kernel<<<(BL * NDIM + 255) / 256, 256>>>();
    scale_kernel<<<(unsigned)(((size_t)BL * CDIM * NDIM / 8 + 255) / 256), 256>>>();
    attnout_kernel<<<dim3(NT, BL, 2), 256, SMEM_ATT>>>();
    epilogue_kernel<<<(unsigned)(((size_t)BDIM * CDIM * NDIM + 255) / 256), 256>>>(x, out);
}